// round 14
// baseline (speedup 1.0000x reference)
#include <cuda_runtime.h>
#include <cuda_fp16.h>
#include <cstdint>

// ---------------------------------------------------------------------------
// MPNN: edge + node MLPs on tensor cores (mma.sync fp16), softmax fused into
// edge kernel (exp without max-subtraction is exact for softmax; logits are
// O(1) here), aggregation via in-kernel red.global, node MLP divides by the
// softmax denominator. Edge kernel: 512 threads, 4x4 warp grid per 128-edge
// tile for latency hiding. d_out = [uh_n (N*64) | uh_e (E*64)] floats.
// ---------------------------------------------------------------------------

#define E_MAX 800000
#define N_MAX 50000

__device__ float  g_den[N_MAX];            // softmax denominators
__device__ float4 g_agg4[N_MAX * 16];      // [N,64] sum(uh_e * ex)

// ---------------------------------------------------------------------------
static __device__ __forceinline__ uint32_t smem_to_u32(const void* p) {
    uint32_t a;
    asm("{ .reg .u64 t; cvta.to.shared.u64 t, %1; cvt.u32.u64 %0, t; }"
        : "=r"(a) : "l"(p));
    return a;
}

static __device__ __forceinline__ void ldsm4(uint32_t& r0, uint32_t& r1,
                                             uint32_t& r2, uint32_t& r3,
                                             uint32_t addr) {
    asm volatile("ldmatrix.sync.aligned.m8n8.x4.shared.b16 {%0,%1,%2,%3}, [%4];"
                 : "=r"(r0), "=r"(r1), "=r"(r2), "=r"(r3) : "r"(addr));
}

static __device__ __forceinline__ void mma16816(float* d, const uint32_t* a,
                                                uint32_t b0, uint32_t b1) {
    asm volatile(
        "mma.sync.aligned.m16n8k16.row.col.f32.f16.f16.f32 "
        "{%0,%1,%2,%3}, {%4,%5,%6,%7}, {%8,%9}, {%0,%1,%2,%3};"
        : "+f"(d[0]), "+f"(d[1]), "+f"(d[2]), "+f"(d[3])
        : "r"(a[0]), "r"(a[1]), "r"(a[2]), "r"(a[3]), "r"(b0), "r"(b1));
}

static __device__ __forceinline__ void red_add2(float* p, float x, float y) {
    asm volatile("red.global.add.v2.f32 [%0], {%1, %2};"
                 :: "l"(p), "f"(x), "f"(y) : "memory");
}

#define CP_ASYNC16(saddr, gptr) \
    asm volatile("cp.async.cg.shared.global [%0], [%1], 16;" \
                 :: "r"(saddr), "l"(gptr))
#define CP_COMMIT() asm volatile("cp.async.commit_group;" ::: "memory")
#define CP_WAIT0()  asm volatile("cp.async.wait_group 0;" ::: "memory")

// ---------------------------------------------------------------------------
__global__ void init_kernel(int N) {
    int i = blockIdx.x * blockDim.x + threadIdx.x;
    if (i < N * 16) g_agg4[i] = make_float4(0.f, 0.f, 0.f, 0.f);
    if (i < N) g_den[i] = 0.f;
}

// ---------------------------------------------------------------------------
// Edge kernel smem layout (byte offsets)
// ---------------------------------------------------------------------------
#define K1P 168   // layer-1 k stride (elems)
#define K2P 136   // layer-2 / node k stride
#define OWB1 0                         // [256][K1P] half = 86016
#define OWB2 86016                     // [64][K2P]  half = 17408
#define OEA  103424                    // e_in [128][K1P]; aliased h [128][K2P]
#define OB1B 146432                    // float[256]  [be1|ba1]
#define OB2B 147456                    // float[64]   be2
#define OWA2 147712                    // float[128]  Wa2
#define OLGP 148224                    // float[256]  logit partials
#define OSDT 149248                    // int[128]    dst per edge
#define OSEF 149760                    // fp32 ef prefetch 2x[128][36]
#define SMEM_EDGE_BYTES 186624

// convert 4 floats -> 4 fp16 and store as one 8-byte chunk
static __device__ __forceinline__ uint32_t h2_as_u32(half2 h) {
    union { half2 h; uint32_t u; } c;
    c.h = h;
    return c.u;
}
static __device__ __forceinline__ void conv_store4(half* hp, float4 v) {
    uint2 u;
    u.x = h2_as_u32(__floats2half2_rn(v.x, v.y));
    u.y = h2_as_u32(__floats2half2_rn(v.z, v.w));
    *(uint2*)(hp) = u;
}

__global__ void __launch_bounds__(512, 1)
edge_kernel(const float* __restrict__ nf, const float* __restrict__ ef,
            const int* __restrict__ src, const int* __restrict__ dst,
            const float* __restrict__ We1, const float* __restrict__ be1,
            const float* __restrict__ We2, const float* __restrict__ be2,
            const float* __restrict__ Wa1, const float* __restrict__ ba1,
            const float* __restrict__ Wa2, const float* __restrict__ ba2,
            float* __restrict__ outE, int E) {
    extern __shared__ char smc[];
    const uint32_t smem_base = smem_to_u32(smc);
    half*  wb1  = (half*)(smc + OWB1);
    half*  wb2  = (half*)(smc + OWB2);
    half*  eah  = (half*)(smc + OEA);
    float* b1s  = (float*)(smc + OB1B);
    float* b2s  = (float*)(smc + OB2B);
    float* wa2s = (float*)(smc + OWA2);
    float* lgp  = (float*)(smc + OLGP);
    int*   sdt  = (int*)(smc + OSDT);
    float* sef  = (float*)(smc + OSEF);

    const int tid    = threadIdx.x;
    const int lane   = tid & 31;
    const int warp   = tid >> 5;
    const int warp_m = warp >> 2;     // 0..3  (32 edges each)
    const int warp_n = warp & 3;      // 0..3

    // ---- stage weights (transposed to [n][k], fp16) ----
    for (int i = tid; i < 160 * 128; i += 512) {
        int k = i >> 7, n = i & 127;
        wb1[n * K1P + k]         = __float2half_rn(We1[i]);
        wb1[(n + 128) * K1P + k] = __float2half_rn(Wa1[i]);
    }
    for (int i = tid; i < 128 * 64; i += 512) {
        int k = i >> 6, n = i & 63;
        wb2[n * K2P + k] = __float2half_rn(We2[i]);
    }
    for (int i = tid; i < 128; i += 512) {
        b1s[i] = be1[i]; b1s[128 + i] = ba1[i]; wa2s[i] = Wa2[i];
    }
    if (tid < 64) b2s[tid] = be2[tid];
    const float ba2v = ba2[0];
    __syncthreads();

    // ldmatrix lane addressing
    const int row_l = ((lane >> 3) & 1) * 8 + (lane & 7);
    const int kb    = (lane >> 4) * 8;
    const int q     = lane >> 2;    // lane/4
    const int r2q   = (lane & 3) * 2;

    const float4* nf4 = (const float4*)nf;
    float* aggf = (float*)g_agg4;
    const int nTiles = (E + 127) >> 7;
    const int edge = tid >> 2;        // 0..127
    const int qq4  = tid & 3;         // staging quarter

    // ---- prefetch ef for first tile (quarter 3: one thread per edge) ----
    if (blockIdx.x < nTiles && qq4 == 3) {
        int eidx = min(blockIdx.x * 128 + edge, E - 1);
        const char* gp = (const char*)(ef + (size_t)eidx * 32);
        uint32_t sp = smem_base + OSEF + (uint32_t)(edge * 144);
#pragma unroll
        for (int c = 0; c < 8; c++) CP_ASYNC16(sp + c * 16, gp + c * 16);
    }
    CP_COMMIT();

    int it = 0;
    for (int tile = blockIdx.x; tile < nTiles; tile += gridDim.x, it++) {
        const int e0 = tile << 7;
        const int ne = min(128, E - e0);
        const int cur = it & 1;

        CP_WAIT0();   // ef for this tile resident

        // ======== stage e_in (gather + fp16 convert), 4 threads/edge =======
        {
            const int eidx = min(e0 + edge, E - 1);
            half* hr = eah + edge * K1P;
            if (qq4 == 0) {
                const float4* ps = nf4 + (size_t)src[eidx] * 16;
#pragma unroll
                for (int c = 0; c < 10; c++)
                    conv_store4(hr + 4 * c, ps[c]);
            } else if (qq4 == 1) {
                const float4* ps = nf4 + (size_t)src[eidx] * 16;
                const float4* pd = nf4 + (size_t)dst[eidx] * 16;
#pragma unroll
                for (int c = 10; c < 16; c++)
                    conv_store4(hr + 4 * c, ps[c]);
#pragma unroll
                for (int c = 0; c < 4; c++)
                    conv_store4(hr + 64 + 4 * c, pd[c]);
            } else if (qq4 == 2) {
                const int didx = dst[eidx];
                sdt[edge] = didx;
                const float4* pd = nf4 + (size_t)didx * 16;
#pragma unroll
                for (int c = 4; c < 14; c++)
                    conv_store4(hr + 64 + 4 * c, pd[c]);
            } else {
                const float4* pd = nf4 + (size_t)dst[eidx] * 16;
#pragma unroll
                for (int c = 14; c < 16; c++)
                    conv_store4(hr + 64 + 4 * c, pd[c]);
                const float* sp = sef + cur * 4608 + edge * 36;
#pragma unroll
                for (int c = 0; c < 8; c++)
                    conv_store4(hr + 128 + 4 * c, *(const float4*)(sp + 4 * c));
                // prefetch next tile's ef
                int tn = tile + gridDim.x;
                if (tn < nTiles) {
                    int eidx2 = min(tn * 128 + edge, E - 1);
                    const char* gp = (const char*)(ef + (size_t)eidx2 * 32);
                    uint32_t spn = smem_base + OSEF +
                                   (uint32_t)((1 - cur) * 18432 + edge * 144);
#pragma unroll
                    for (int c = 0; c < 8; c++)
                        CP_ASYNC16(spn + c * 16, gp + c * 16);
                }
            }
            CP_COMMIT();
        }
        __syncthreads();

        // ================= layer 1: D1[128][256] =================
        float acc[2][8][4];
#pragma unroll
        for (int mt = 0; mt < 2; mt++)
#pragma unroll
            for (int nt = 0; nt < 8; nt++)
#pragma unroll
                for (int j = 0; j < 4; j++) acc[mt][nt][j] = 0.f;

        uint32_t ah_addr[2];
#pragma unroll
        for (int mt = 0; mt < 2; mt++) {
            int row = warp_m * 32 + mt * 16 + row_l;
            ah_addr[mt] = smem_base + OEA + (uint32_t)(row * K1P + kb) * 2;
        }

#pragma unroll 1
        for (int ks = 0; ks < 10; ks++) {
            const int k0 = ks * 16;
            uint32_t ah[2][4];
#pragma unroll
            for (int mt = 0; mt < 2; mt++)
                ldsm4(ah[mt][0], ah[mt][1], ah[mt][2], ah[mt][3],
                      ah_addr[mt] + k0 * 2);
#pragma unroll
            for (int nt = 0; nt < 8; nt++) {
                const half* bp = wb1 + (warp_n * 64 + nt * 8 + q) * K1P + k0 + r2q;
                uint32_t b0 = *(const uint32_t*)(bp);
                uint32_t b1 = *(const uint32_t*)(bp + 8);
#pragma unroll
                for (int mt = 0; mt < 2; mt++)
                    mma16816(acc[mt][nt], ah[mt], b0, b1);
            }
        }
        __syncthreads();   // all e_in reads done (h aliases e_in buffer)

        // ================= epilogue 1 =================
        if (warp_n < 2) {
            // h = relu(D1[:, :128] + be1) -> fp16 [edge][K2P]
#pragma unroll
            for (int mt = 0; mt < 2; mt++) {
                int er = warp_m * 32 + mt * 16 + q;
#pragma unroll
                for (int nt = 0; nt < 8; nt++) {
                    int c = warp_n * 64 + nt * 8 + r2q;
                    float bb0 = b1s[c], bb1 = b1s[c + 1];
                    float v0 = fmaxf(acc[mt][nt][0] + bb0, 0.f);
                    float v1 = fmaxf(acc[mt][nt][1] + bb1, 0.f);
                    float v2 = fmaxf(acc[mt][nt][2] + bb0, 0.f);
                    float v3 = fmaxf(acc[mt][nt][3] + bb1, 0.f);
                    *(half2*)(eah + er * K2P + c) = __floats2half2_rn(v0, v1);
                    *(half2*)(eah + (er + 8) * K2P + c) =
                        __floats2half2_rn(v2, v3);
                }
            }
        } else {
            // attention logit partials from D1[:, 128:256]
            float s[2][2];
#pragma unroll
            for (int mt = 0; mt < 2; mt++) { s[mt][0] = 0.f; s[mt][1] = 0.f; }
#pragma unroll
            for (int mt = 0; mt < 2; mt++)
#pragma unroll
                for (int nt = 0; nt < 8; nt++) {
                    int c = warp_n * 64 + nt * 8 + r2q;   // 128..255
                    float bb0 = b1s[c], bb1 = b1s[c + 1];
                    float w0 = wa2s[c - 128], w1 = wa2s[c - 127];
                    s[mt][0] += fmaxf(acc[mt][nt][0] + bb0, 0.f) * w0 +
                                fmaxf(acc[mt][nt][1] + bb1, 0.f) * w1;
                    s[mt][1] += fmaxf(acc[mt][nt][2] + bb0, 0.f) * w0 +
                                fmaxf(acc[mt][nt][3] + bb1, 0.f) * w1;
                }
#pragma unroll
            for (int mt = 0; mt < 2; mt++)
#pragma unroll
                for (int hh2 = 0; hh2 < 2; hh2++) {
                    float v = s[mt][hh2];
                    v += __shfl_xor_sync(0xffffffffu, v, 1);
                    v += __shfl_xor_sync(0xffffffffu, v, 2);
                    if ((lane & 3) == 0)
                        lgp[(warp_n - 2) * 128 + warp_m * 32 + mt * 16 + q +
                            hh2 * 8] = v;
                }
        }
        __syncthreads();   // h + lgp visible

        // ---- denominator reduction (overlaps layer-2; store phase
        //      recomputes the identical __expf from lgp) ----
        if (tid < ne) {
            float ex = __expf(lgp[tid] + lgp[128 + tid] + ba2v);
            asm volatile("red.global.add.f32 [%0], %1;"
                         :: "l"(&g_den[sdt[tid]]), "f"(ex) : "memory");
        }

        // ================= layer 2: D2[128][64] = h @ We2t =================
        float acc2[2][2][4];
#pragma unroll
        for (int mt = 0; mt < 2; mt++)
#pragma unroll
            for (int nt = 0; nt < 2; nt++)
#pragma unroll
                for (int j = 0; j < 4; j++) acc2[mt][nt][j] = 0.f;

        uint32_t ah2[2];
#pragma unroll
        for (int mt = 0; mt < 2; mt++) {
            int row = warp_m * 32 + mt * 16 + row_l;
            ah2[mt] = smem_base + OEA + (uint32_t)(row * K2P + kb) * 2;
        }

#pragma unroll 1
        for (int ks = 0; ks < 8; ks++) {
            const int k0 = ks * 16;
            uint32_t ah[2][4];
#pragma unroll
            for (int mt = 0; mt < 2; mt++)
                ldsm4(ah[mt][0], ah[mt][1], ah[mt][2], ah[mt][3],
                      ah2[mt] + k0 * 2);
#pragma unroll
            for (int nt = 0; nt < 2; nt++) {
                const half* bp = wb2 + (warp_n * 16 + nt * 8 + q) * K2P + k0 + r2q;
                uint32_t b0 = *(const uint32_t*)(bp);
                uint32_t b1 = *(const uint32_t*)(bp + 8);
#pragma unroll
                for (int mt = 0; mt < 2; mt++)
                    mma16816(acc2[mt][nt], ah[mt], b0, b1);
            }
        }

        // ---- store uh_e + fused weighted aggregation ----
#pragma unroll
        for (int mt = 0; mt < 2; mt++) {
            int er = warp_m * 32 + mt * 16 + q;
            float a0 = __expf(lgp[er] + lgp[128 + er] + ba2v);
            float a1 = __expf(lgp[er + 8] + lgp[128 + er + 8] + ba2v);
            int   d0 = sdt[er], d1 = sdt[er + 8];
#pragma unroll
            for (int nt = 0; nt < 2; nt++) {
                int c = warp_n * 16 + nt * 8 + r2q;
                float bb0 = b2s[c], bb1 = b2s[c + 1];
                if (er < ne) {
                    float x = acc2[mt][nt][0] + bb0;
                    float y = acc2[mt][nt][1] + bb1;
                    *(float2*)&outE[(size_t)(e0 + er) * 64 + c] =
                        make_float2(x, y);
                    red_add2(aggf + (size_t)d0 * 64 + c, x * a0, y * a0);
                }
                if (er + 8 < ne) {
                    float x = acc2[mt][nt][2] + bb0;
                    float y = acc2[mt][nt][3] + bb1;
                    *(float2*)&outE[(size_t)(e0 + er + 8) * 64 + c] =
                        make_float2(x, y);
                    red_add2(aggf + (size_t)d1 * 64 + c, x * a1, y * a1);
                }
            }
        }
        __syncthreads();   // protect smem before next tile
    }
}

// ---------------------------------------------------------------------------
// K_node: fp16 tensor cores; uh_n = MLP([agg/den | nf]); 2 CTAs/SM.
// ---------------------------------------------------------------------------
#define NWB1 0                         // [128][K2P] half = 34816
#define NWB2 34816                     // [64][K2P]  half = 17408
#define NXA  52224                     // x [128][K2P] half; aliased h
#define NB1B 87040                     // float[128]
#define NB2B 87552                     // float[64]
#define SMEM_NODE_BYTES 87808

__global__ void __launch_bounds__(256, 2)
node_kernel(const float* __restrict__ nf,
            const float* __restrict__ Wn1, const float* __restrict__ bn1,
            const float* __restrict__ Wn2, const float* __restrict__ bn2,
            float* __restrict__ outN, int N) {
    extern __shared__ char smc[];
    const uint32_t smem_base = smem_to_u32(smc);
    half*  wb1 = (half*)(smc + NWB1);
    half*  wb2 = (half*)(smc + NWB2);
    half*  xa  = (half*)(smc + NXA);
    float* b1s = (float*)(smc + NB1B);
    float* b2s = (float*)(smc + NB2B);

    const int tid    = threadIdx.x;
    const int lane   = tid & 31;
    const int warp   = tid >> 5;
    const int warp_m = warp >> 2;     // 0..1
    const int warp_n = warp & 3;      // 0..3

    for (int i = tid; i < 128 * 128; i += 256) {
        int k = i >> 7, n = i & 127;
        wb1[n * K2P + k] = __float2half_rn(Wn1[i]);
    }
    for (int i = tid; i < 128 * 64; i += 256) {
        int k = i >> 6, n = i & 63;
        wb2[n * K2P + k] = __float2half_rn(Wn2[i]);
    }
    for (int i = tid; i < 128; i += 256) b1s[i] = bn1[i];
    if (tid < 64) b2s[tid] = bn2[tid];
    __syncthreads();

    const int row_l = ((lane >> 3) & 1) * 8 + (lane & 7);
    const int kb    = (lane >> 4) * 8;
    const int q     = lane >> 2;
    const int r2q   = (lane & 3) * 2;

    const float4* nf4 = (const float4*)nf;
    const int nTiles = (N + 127) >> 7;
    const int node = tid >> 1;
    const int hh   = tid & 1;

    for (int tile = blockIdx.x; tile < nTiles; tile += gridDim.x) {
        const int n0 = tile << 7;
        const int nn = min(128, N - n0);

        // ---- stage x = [agg/den | nf] as fp16 [128][K2P] ----
        {
            const int gn = min(n0 + node, N - 1);
            half* hr = xa + node * K2P;
            if (hh == 0) {
                float invd = 1.f / fmaxf(g_den[gn], 1e-38f);
                const float4* pa = &g_agg4[(size_t)gn * 16];
#pragma unroll
                for (int qq = 0; qq < 16; qq++) {
                    float4 v = pa[qq];
                    v.x *= invd; v.y *= invd; v.z *= invd; v.w *= invd;
                    conv_store4(hr + 4 * qq, v);
                }
            } else {
                const float4* pn = nf4 + (size_t)gn * 16;
#pragma unroll
                for (int qq = 0; qq < 16; qq++)
                    conv_store4(hr + 64 + 4 * qq, pn[qq]);
            }
        }
        __syncthreads();

        // ---- layer 1: D[128][128] ----
        float acc[4][4][4];
#pragma unroll
        for (int mt = 0; mt < 4; mt++)
#pragma unroll
            for (int nt = 0; nt < 4; nt++)
#pragma unroll
                for (int j = 0; j < 4; j++) acc[mt][nt][j] = 0.f;

        uint32_t ah_addr[4];
#pragma unroll
        for (int mt = 0; mt < 4; mt++) {
            int row = warp_m * 64 + mt * 16 + row_l;
            ah_addr[mt] = smem_base + NXA + (uint32_t)(row * K2P + kb) * 2;
        }

#pragma unroll 1
        for (int ks = 0; ks < 8; ks++) {
            const int k0 = ks * 16;
            uint32_t ah[4][4];
#pragma unroll
            for (int mt = 0; mt < 4; mt++)
                ldsm4(ah[mt][0], ah[mt][1], ah[mt][2], ah[mt][3],
                      ah_addr[mt] + k0 * 2);
#pragma unroll
            for (int nt = 0; nt < 4; nt++) {
                const half* bp = wb1 + (warp_n * 32 + nt * 8 + q) * K2P + k0 + r2q;
                uint32_t b0 = *(const uint32_t*)(bp);
                uint32_t b1 = *(const uint32_t*)(bp + 8);
#pragma unroll
                for (int mt = 0; mt < 4; mt++)
                    mma16816(acc[mt][nt], ah[mt], b0, b1);
            }
        }
        __syncthreads();

        // ---- h = relu(D + bn1) -> fp16 in place ----
#pragma unroll
        for (int mt = 0; mt < 4; mt++) {
            int er = warp_m * 64 + mt * 16 + q;
#pragma unroll
            for (int nt = 0; nt < 4; nt++) {
                int c = warp_n * 32 + nt * 8 + r2q;
                float bb0 = b1s[c], bb1 = b1s[c + 1];
                float v0 = fmaxf(acc[mt][nt][0] + bb0, 0.f);
                float v1 = fmaxf(acc[mt][nt][1] + bb1, 0.f);
                float v2 = fmaxf(acc[mt][nt][2] + bb0, 0.f);
                float v3 = fmaxf(acc[mt][nt][3] + bb1, 0.f);
                *(half2*)(xa + er * K2P + c) = __floats2half2_rn(v0, v1);
                *(half2*)(xa + (er + 8) * K2P + c) = __floats2half2_rn(v2, v3);
            }
        }
        __syncthreads();

        // ---- layer 2: D2[128][64] ----
        float acc2[4][2][4];
#pragma unroll
        for (int mt = 0; mt < 4; mt++)
#pragma unroll
            for (int nt = 0; nt < 2; nt++)
#pragma unroll
                for (int j = 0; j < 4; j++) acc2[mt][nt][j] = 0.f;

#pragma unroll 1
        for (int ks = 0; ks < 8; ks++) {
            const int k0 = ks * 16;
            uint32_t ah[4][4];
#pragma unroll
            for (int mt = 0; mt < 4; mt++)
                ldsm4(ah[mt][0], ah[mt][1], ah[mt][2], ah[mt][3],
                      ah_addr[mt] + k0 * 2);
#pragma unroll
            for (int nt = 0; nt < 2; nt++) {
                const half* bp = wb2 + (warp_n * 16 + nt * 8 + q) * K2P + k0 + r2q;
                uint32_t b0 = *(const uint32_t*)(bp);
                uint32_t b1 = *(const uint32_t*)(bp + 8);
#pragma unroll
                for (int mt = 0; mt < 4; mt++)
                    mma16816(acc2[mt][nt], ah[mt], b0, b1);
            }
        }

        // ---- store uh_n ----
#pragma unroll
        for (int mt = 0; mt < 4; mt++) {
            int er = warp_m * 64 + mt * 16 + q;
#pragma unroll
            for (int nt = 0; nt < 2; nt++) {
                int c = warp_n * 16 + nt * 8 + r2q;
                float bb0 = b2s[c], bb1 = b2s[c + 1];
                if (er < nn)
                    *(float2*)&outN[(size_t)(n0 + er) * 64 + c] =
                        make_float2(acc2[mt][nt][0] + bb0,
                                    acc2[mt][nt][1] + bb1);
                if (er + 8 < nn)
                    *(float2*)&outN[(size_t)(n0 + er + 8) * 64 + c] =
                        make_float2(acc2[mt][nt][2] + bb0,
                                    acc2[mt][nt][3] + bb1);
            }
        }
        __syncthreads();
    }
}

// ---------------------------------------------------------------------------
extern "C" void kernel_launch(void* const* d_in, const int* in_sizes, int n_in,
                              void* d_out, int out_size) {
    const float* nf  = (const float*)d_in[0];
    const float* ef  = (const float*)d_in[1];
    const int*   src = (const int*)d_in[2];
    const int*   dst = (const int*)d_in[3];
    const float* We1 = (const float*)d_in[4];
    const float* be1 = (const float*)d_in[5];
    const float* We2 = (const float*)d_in[6];
    const float* be2 = (const float*)d_in[7];
    const float* Wa1 = (const float*)d_in[8];
    const float* ba1 = (const float*)d_in[9];
    const float* Wa2 = (const float*)d_in[10];
    const float* ba2 = (const float*)d_in[11];
    const float* Wn1 = (const float*)d_in[12];
    const float* bn1 = (const float*)d_in[13];
    const float* Wn2 = (const float*)d_in[14];
    const float* bn2 = (const float*)d_in[15];

    int E = in_sizes[2];
    int N = in_sizes[0] / 64;
    if (E > E_MAX) E = E_MAX;
    if (N > N_MAX) N = N_MAX;

    float* outN = (float*)d_out;
    float* outE = outN + (size_t)N * 64;

    cudaFuncSetAttribute(edge_kernel,
                         cudaFuncAttributeMaxDynamicSharedMemorySize,
                         SMEM_EDGE_BYTES);
    cudaFuncSetAttribute(node_kernel,
                         cudaFuncAttributeMaxDynamicSharedMemorySize,
                         SMEM_NODE_BYTES);

    int nsm = 148;
    cudaDeviceGetAttribute(&nsm, cudaDevAttrMultiProcessorCount, 0);

    init_kernel<<<(N * 16 + 255) / 256, 256>>>(N);
    edge_kernel<<<nsm, 512, SMEM_EDGE_BYTES>>>(
        nf, ef, src, dst, We1, be1, We2, be2, Wa1, ba1, Wa2, ba2, outE, E);
    node_kernel<<<2 * nsm, 256, SMEM_NODE_BYTES>>>(
        nf, Wn1, bn1, Wn2, bn2, outN, N);
}

// round 16
// speedup vs baseline: 1.0732x; 1.0732x over previous
#include <cuda_runtime.h>
#include <cuda_fp16.h>
#include <cstdint>

// ---------------------------------------------------------------------------
// MPNN: edge + node MLPs on tensor cores (mma.sync fp16), softmax fused into
// edge kernel (exp without max-subtraction is exact for softmax; logits are
// O(1) here), aggregation via in-kernel red.global, node MLP divides by the
// softmax denominator. Edge kernel: 256 threads, 2x4 warp grid, 128-edge
// tiles; B weights stored k-permuted so fragments load as single LDS.64;
// src/dst indices + ef prefetched with cp.async double buffering (barrier
// after wait_group orders producer-thread completion for all consumers).
// d_out = [uh_n (N*64) | uh_e (E*64)] floats.
// ---------------------------------------------------------------------------

#define E_MAX 800000
#define N_MAX 50000

__device__ float  g_den[N_MAX];            // softmax denominators
__device__ float4 g_agg4[N_MAX * 16];      // [N,64] sum(uh_e * ex)

// ---------------------------------------------------------------------------
static __device__ __forceinline__ uint32_t smem_to_u32(const void* p) {
    uint32_t a;
    asm("{ .reg .u64 t; cvta.to.shared.u64 t, %1; cvt.u32.u64 %0, t; }"
        : "=r"(a) : "l"(p));
    return a;
}

static __device__ __forceinline__ void ldsm4(uint32_t& r0, uint32_t& r1,
                                             uint32_t& r2, uint32_t& r3,
                                             uint32_t addr) {
    asm volatile("ldmatrix.sync.aligned.m8n8.x4.shared.b16 {%0,%1,%2,%3}, [%4];"
                 : "=r"(r0), "=r"(r1), "=r"(r2), "=r"(r3) : "r"(addr));
}

static __device__ __forceinline__ void mma16816(float* d, const uint32_t* a,
                                                uint32_t b0, uint32_t b1) {
    asm volatile(
        "mma.sync.aligned.m16n8k16.row.col.f32.f16.f16.f32 "
        "{%0,%1,%2,%3}, {%4,%5,%6,%7}, {%8,%9}, {%0,%1,%2,%3};"
        : "+f"(d[0]), "+f"(d[1]), "+f"(d[2]), "+f"(d[3])
        : "r"(a[0]), "r"(a[1]), "r"(a[2]), "r"(a[3]), "r"(b0), "r"(b1));
}

static __device__ __forceinline__ void red_add2(float* p, float x, float y) {
    asm volatile("red.global.add.v2.f32 [%0], {%1, %2};"
                 :: "l"(p), "f"(x), "f"(y) : "memory");
}

#define CP_ASYNC16(saddr, gptr) \
    asm volatile("cp.async.cg.shared.global [%0], [%1], 16;" \
                 :: "r"(saddr), "l"(gptr))
#define CP_COMMIT() asm volatile("cp.async.commit_group;" ::: "memory")
#define CP_WAIT0()  asm volatile("cp.async.wait_group 0;" ::: "memory")

// within-16 k-permutation: {2m,2m+1,8+2m,8+2m+1} -> positions 4m..4m+3
static __device__ __forceinline__ int kperm(int k) {
    int j = k & 15;
    return (k & ~15) + (((j >> 1) & 3) * 4) + (j & 1) + (((j >> 3) & 1) * 2);
}

// ---------------------------------------------------------------------------
__global__ void init_kernel(int N) {
    int i = blockIdx.x * blockDim.x + threadIdx.x;
    if (i < N * 16) g_agg4[i] = make_float4(0.f, 0.f, 0.f, 0.f);
    if (i < N) g_den[i] = 0.f;
}

// ---------------------------------------------------------------------------
// Edge kernel smem layout (byte offsets)
// ---------------------------------------------------------------------------
#define K1P 168   // layer-1 k stride (elems)
#define K2P 136   // layer-2 / node k stride
#define OWB1 0                         // [256][K1P] half = 86016 (k-permuted)
#define OWB2 86016                     // [64][K2P]  half = 17408 (k-permuted)
#define OEA  103424                    // e_in [128][K1P]; aliased h [128][K2P]
#define OB1B 146432                    // float[256]  [be1|ba1]
#define OB2B 147456                    // float[64]   be2
#define OWA2 147712                    // float[128]  Wa2
#define OLGP 148224                    // float[256]  logit partials
#define OSDT 149248                    // int[128]    dst per edge
#define OSEF 149760                    // fp32 ef prefetch 2x[128][36]
#define OSIP 186624                    // int src prefetch 2x128
#define ODIP 187648                    // int dst prefetch 2x128
#define SMEM_EDGE_BYTES 188672

// convert 4 floats -> 4 fp16 and store as one 8-byte chunk
static __device__ __forceinline__ uint32_t h2_as_u32(half2 h) {
    union { half2 h; uint32_t u; } c;
    c.h = h;
    return c.u;
}
static __device__ __forceinline__ void conv_store4(half* hp, float4 v) {
    uint2 u;
    u.x = h2_as_u32(__floats2half2_rn(v.x, v.y));
    u.y = h2_as_u32(__floats2half2_rn(v.z, v.w));
    *(uint2*)(hp) = u;
}

__global__ void __launch_bounds__(256, 1)
edge_kernel(const float* __restrict__ nf, const float* __restrict__ ef,
            const int* __restrict__ src, const int* __restrict__ dst,
            const float* __restrict__ We1, const float* __restrict__ be1,
            const float* __restrict__ We2, const float* __restrict__ be2,
            const float* __restrict__ Wa1, const float* __restrict__ ba1,
            const float* __restrict__ Wa2, const float* __restrict__ ba2,
            float* __restrict__ outE, int E) {
    extern __shared__ char smc[];
    const uint32_t smem_base = smem_to_u32(smc);
    half*  wb1  = (half*)(smc + OWB1);
    half*  wb2  = (half*)(smc + OWB2);
    half*  eah  = (half*)(smc + OEA);
    float* b1s  = (float*)(smc + OB1B);
    float* b2s  = (float*)(smc + OB2B);
    float* wa2s = (float*)(smc + OWA2);
    float* lgp  = (float*)(smc + OLGP);
    int*   sdt  = (int*)(smc + OSDT);
    float* sef  = (float*)(smc + OSEF);
    int*   sip  = (int*)(smc + OSIP);
    int*   dip  = (int*)(smc + ODIP);

    const int tid    = threadIdx.x;
    const int lane   = tid & 31;
    const int warp   = tid >> 5;
    const int warp_m = warp >> 2;     // 0..1
    const int warp_n = warp & 3;      // 0..3

    // ---- stage weights (transposed to [n][k-permuted], fp16) ----
    for (int i = tid; i < 160 * 128; i += 256) {
        int k = i >> 7, n = i & 127;
        int kp = kperm(k);
        wb1[n * K1P + kp]         = __float2half_rn(We1[i]);
        wb1[(n + 128) * K1P + kp] = __float2half_rn(Wa1[i]);
    }
    for (int i = tid; i < 128 * 64; i += 256) {
        int k = i >> 6, n = i & 63;
        wb2[n * K2P + kperm(k)] = __float2half_rn(We2[i]);
    }
    for (int i = tid; i < 128; i += 256) {
        b1s[i] = be1[i]; b1s[128 + i] = ba1[i]; wa2s[i] = Wa2[i];
    }
    if (tid < 64) b2s[tid] = be2[tid];
    const float ba2v = ba2[0];
    __syncthreads();

    // ldmatrix / fragment lane addressing
    const int row_l = ((lane >> 3) & 1) * 8 + (lane & 7);
    const int kb    = (lane >> 4) * 8;
    const int q     = lane >> 2;        // lane/4
    const int r2q   = (lane & 3) * 2;
    const int r4q   = (lane & 3) * 4;   // permuted B fragment offset

    const float4* nf4 = (const float4*)nf;
    float* aggf = (float*)g_agg4;
    const int nTiles = (E + 127) >> 7;
    const int edge = tid >> 1;
    const int hh   = tid & 1;

    // ---- prefetch ef + indices for first tile ----
    if (blockIdx.x < nTiles) {
        if (hh == 1) {
            int eidx = min(blockIdx.x * 128 + edge, E - 1);
            const char* gp = (const char*)(ef + (size_t)eidx * 32);
            uint32_t sp = smem_base + OSEF + (uint32_t)(edge * 144);
#pragma unroll
            for (int c = 0; c < 8; c++) CP_ASYNC16(sp + c * 16, gp + c * 16);
        }
        if ((blockIdx.x + 1) * 128 <= E) {
            if (tid < 32)
                CP_ASYNC16(smem_base + OSIP + tid * 16,
                           (const char*)src + (size_t)blockIdx.x * 512 + tid * 16);
            else if (tid < 64)
                CP_ASYNC16(smem_base + ODIP + (tid - 32) * 16,
                           (const char*)dst + (size_t)blockIdx.x * 512 +
                               (tid - 32) * 16);
        }
    }
    CP_COMMIT();

    int it = 0;
    for (int tile = blockIdx.x; tile < nTiles; tile += gridDim.x, it++) {
        const int e0 = tile << 7;
        const int ne = min(128, E - e0);
        const int cur = it & 1;

        CP_WAIT0();        // producers' groups complete
        __syncthreads();   // make producer-issued cp.async data visible to ALL

        // ================= stage e_in (gather + fp16 convert) ==============
        {
            const int eidx = min(e0 + edge, E - 1);
            int sidx, didx;
            if (ne == 128) {
                sidx = sip[cur * 128 + edge];
                didx = dip[cur * 128 + edge];
            } else {
                sidx = src[eidx];
                didx = dst[eidx];
            }
            half* hr = eah + edge * K1P;
            if (hh == 0) {
                sdt[edge] = didx;
                const float4* ps = nf4 + (size_t)sidx * 16;
#pragma unroll
                for (int qq = 0; qq < 16; qq++)
                    conv_store4(hr + 4 * qq, ps[qq]);
                const float4* pd = nf4 + (size_t)didx * 16;
#pragma unroll
                for (int qq = 0; qq < 4; qq++)
                    conv_store4(hr + 64 + 4 * qq, pd[qq]);
            } else {
                const float4* pd = nf4 + (size_t)didx * 16;
#pragma unroll
                for (int qq = 4; qq < 16; qq++)
                    conv_store4(hr + 64 + 4 * qq, pd[qq]);
                const float* sp = sef + cur * 4608 + edge * 36;
#pragma unroll
                for (int qq = 0; qq < 8; qq++)
                    conv_store4(hr + 128 + 4 * qq, *(const float4*)(sp + 4 * qq));
                // prefetch next tile's ef + indices
                int tn = tile + gridDim.x;
                if (tn < nTiles) {
                    int eidx2 = min(tn * 128 + edge, E - 1);
                    const char* gp = (const char*)(ef + (size_t)eidx2 * 32);
                    uint32_t spn = smem_base + OSEF +
                                   (uint32_t)((1 - cur) * 18432 + edge * 144);
#pragma unroll
                    for (int c = 0; c < 8; c++)
                        CP_ASYNC16(spn + c * 16, gp + c * 16);
                    if ((tn + 1) * 128 <= E) {
                        if (edge < 32)
                            CP_ASYNC16(smem_base + OSIP + (1 - cur) * 512 +
                                           edge * 16,
                                       (const char*)src + (size_t)tn * 512 +
                                           edge * 16);
                        else if (edge < 64)
                            CP_ASYNC16(smem_base + ODIP + (1 - cur) * 512 +
                                           (edge - 32) * 16,
                                       (const char*)dst + (size_t)tn * 512 +
                                           (edge - 32) * 16);
                    }
                }
            }
            CP_COMMIT();
        }
        __syncthreads();

        // ================= layer 1: D1[128][256] =================
        float acc[4][8][4];
#pragma unroll
        for (int mt = 0; mt < 4; mt++)
#pragma unroll
            for (int nt = 0; nt < 8; nt++)
#pragma unroll
                for (int j = 0; j < 4; j++) acc[mt][nt][j] = 0.f;

        uint32_t ah_addr[4];
#pragma unroll
        for (int mt = 0; mt < 4; mt++) {
            int row = warp_m * 64 + mt * 16 + row_l;
            ah_addr[mt] = smem_base + OEA + (uint32_t)(row * K1P + kb) * 2;
        }

#pragma unroll 1
        for (int ks = 0; ks < 10; ks++) {
            const int k0 = ks * 16;
            uint32_t ah[4][4];
#pragma unroll
            for (int mt = 0; mt < 4; mt++)
                ldsm4(ah[mt][0], ah[mt][1], ah[mt][2], ah[mt][3],
                      ah_addr[mt] + k0 * 2);
#pragma unroll
            for (int nt = 0; nt < 8; nt++) {
                const half* bp =
                    wb1 + (warp_n * 64 + nt * 8 + q) * K1P + k0 + r4q;
                uint2 bu = *(const uint2*)(bp);
#pragma unroll
                for (int mt = 0; mt < 4; mt++)
                    mma16816(acc[mt][nt], ah[mt], bu.x, bu.y);
            }
        }
        __syncthreads();   // all e_in reads done (h aliases e_in buffer)

        // ================= epilogue 1 =================
        if (warp_n < 2) {
            // h = relu(D1[:, :128] + be1) -> fp16 [edge][K2P]
#pragma unroll
            for (int mt = 0; mt < 4; mt++) {
                int er = warp_m * 64 + mt * 16 + q;
#pragma unroll
                for (int nt = 0; nt < 8; nt++) {
                    int c = warp_n * 64 + nt * 8 + r2q;
                    float bb0 = b1s[c], bb1 = b1s[c + 1];
                    float v0 = fmaxf(acc[mt][nt][0] + bb0, 0.f);
                    float v1 = fmaxf(acc[mt][nt][1] + bb1, 0.f);
                    float v2 = fmaxf(acc[mt][nt][2] + bb0, 0.f);
                    float v3 = fmaxf(acc[mt][nt][3] + bb1, 0.f);
                    *(half2*)(eah + er * K2P + c) = __floats2half2_rn(v0, v1);
                    *(half2*)(eah + (er + 8) * K2P + c) =
                        __floats2half2_rn(v2, v3);
                }
            }
        } else {
            // attention logit partials from D1[:, 128:256]
            float s[4][2];
#pragma unroll
            for (int mt = 0; mt < 4; mt++) { s[mt][0] = 0.f; s[mt][1] = 0.f; }
#pragma unroll
            for (int mt = 0; mt < 4; mt++)
#pragma unroll
                for (int nt = 0; nt < 8; nt++) {
                    int c = warp_n * 64 + nt * 8 + r2q;   // 128..255
                    float bb0 = b1s[c], bb1 = b1s[c + 1];
                    float w0 = wa2s[c - 128], w1 = wa2s[c - 127];
                    s[mt][0] += fmaxf(acc[mt][nt][0] + bb0, 0.f) * w0 +
                                fmaxf(acc[mt][nt][1] + bb1, 0.f) * w1;
                    s[mt][1] += fmaxf(acc[mt][nt][2] + bb0, 0.f) * w0 +
                                fmaxf(acc[mt][nt][3] + bb1, 0.f) * w1;
                }
#pragma unroll
            for (int mt = 0; mt < 4; mt++)
#pragma unroll
                for (int hh2 = 0; hh2 < 2; hh2++) {
                    float v = s[mt][hh2];
                    v += __shfl_xor_sync(0xffffffffu, v, 1);
                    v += __shfl_xor_sync(0xffffffffu, v, 2);
                    if ((lane & 3) == 0)
                        lgp[(warp_n - 2) * 128 + warp_m * 64 + mt * 16 + q +
                            hh2 * 8] = v;
                }
        }
        __syncthreads();   // h + lgp visible

        // ---- denominator reduction (overlaps layer-2; store phase
        //      recomputes the identical __expf from lgp) ----
        if (tid < ne) {
            float ex = __expf(lgp[tid] + lgp[128 + tid] + ba2v);
            asm volatile("red.global.add.f32 [%0], %1;"
                         :: "l"(&g_den[sdt[tid]]), "f"(ex) : "memory");
        }

        // ================= layer 2: D2[128][64] = h @ We2t =================
        float acc2[4][2][4];
#pragma unroll
        for (int mt = 0; mt < 4; mt++)
#pragma unroll
            for (int nt = 0; nt < 2; nt++)
#pragma unroll
                for (int j = 0; j < 4; j++) acc2[mt][nt][j] = 0.f;

        uint32_t ah2[4];
#pragma unroll
        for (int mt = 0; mt < 4; mt++) {
            int row = warp_m * 64 + mt * 16 + row_l;
            ah2[mt] = smem_base + OEA + (uint32_t)(row * K2P + kb) * 2;
        }

#pragma unroll 1
        for (int ks = 0; ks < 8; ks++) {
            const int k0 = ks * 16;
            uint32_t ah[4][4];
#pragma unroll
            for (int mt = 0; mt < 4; mt++)
                ldsm4(ah[mt][0], ah[mt][1], ah[mt][2], ah[mt][3],
                      ah2[mt] + k0 * 2);
#pragma unroll
            for (int nt = 0; nt < 2; nt++) {
                const half* bp =
                    wb2 + (warp_n * 16 + nt * 8 + q) * K2P + k0 + r4q;
                uint2 bu = *(const uint2*)(bp);
#pragma unroll
                for (int mt = 0; mt < 4; mt++)
                    mma16816(acc2[mt][nt], ah[mt], bu.x, bu.y);
            }
        }

        // ---- store uh_e + fused weighted aggregation ----
#pragma unroll
        for (int mt = 0; mt < 4; mt++) {
            int er = warp_m * 64 + mt * 16 + q;
            float a0 = __expf(lgp[er] + lgp[128 + er] + ba2v);
            float a1 = __expf(lgp[er + 8] + lgp[128 + er + 8] + ba2v);
            int   d0 = sdt[er], d1 = sdt[er + 8];
#pragma unroll
            for (int nt = 0; nt < 2; nt++) {
                int c = warp_n * 16 + nt * 8 + r2q;
                float bb0 = b2s[c], bb1 = b2s[c + 1];
                if (er < ne) {
                    float x = acc2[mt][nt][0] + bb0;
                    float y = acc2[mt][nt][1] + bb1;
                    *(float2*)&outE[(size_t)(e0 + er) * 64 + c] =
                        make_float2(x, y);
                    red_add2(aggf + (size_t)d0 * 64 + c, x * a0, y * a0);
                }
                if (er + 8 < ne) {
                    float x = acc2[mt][nt][2] + bb0;
                    float y = acc2[mt][nt][3] + bb1;
                    *(float2*)&outE[(size_t)(e0 + er + 8) * 64 + c] =
                        make_float2(x, y);
                    red_add2(aggf + (size_t)d1 * 64 + c, x * a1, y * a1);
                }
            }
        }
        __syncthreads();   // protect smem before next tile
    }
}

// ---------------------------------------------------------------------------
// K_node: fp16 tensor cores; uh_n = MLP([agg/den | nf]); 2 CTAs/SM.
// ---------------------------------------------------------------------------
#define NWB1 0                         // [128][K2P] half = 34816
#define NWB2 34816                     // [64][K2P]  half = 17408
#define NXA  52224                     // x [128][K2P] half; aliased h
#define NB1B 87040                     // float[128]
#define NB2B 87552                     // float[64]
#define SMEM_NODE_BYTES 87808

__global__ void __launch_bounds__(256, 2)
node_kernel(const float* __restrict__ nf,
            const float* __restrict__ Wn1, const float* __restrict__ bn1,
            const float* __restrict__ Wn2, const float* __restrict__ bn2,
            float* __restrict__ outN, int N) {
    extern __shared__ char smc[];
    const uint32_t smem_base = smem_to_u32(smc);
    half*  wb1 = (half*)(smc + NWB1);
    half*  wb2 = (half*)(smc + NWB2);
    half*  xa  = (half*)(smc + NXA);
    float* b1s = (float*)(smc + NB1B);
    float* b2s = (float*)(smc + NB2B);

    const int tid    = threadIdx.x;
    const int lane   = tid & 31;
    const int warp   = tid >> 5;
    const int warp_m = warp >> 2;     // 0..1
    const int warp_n = warp & 3;      // 0..3

    for (int i = tid; i < 128 * 128; i += 256) {
        int k = i >> 7, n = i & 127;
        wb1[n * K2P + kperm(k)] = __float2half_rn(Wn1[i]);
    }
    for (int i = tid; i < 128 * 64; i += 256) {
        int k = i >> 6, n = i & 63;
        wb2[n * K2P + kperm(k)] = __float2half_rn(Wn2[i]);
    }
    for (int i = tid; i < 128; i += 256) b1s[i] = bn1[i];
    if (tid < 64) b2s[tid] = bn2[tid];
    __syncthreads();

    const int row_l = ((lane >> 3) & 1) * 8 + (lane & 7);
    const int kb    = (lane >> 4) * 8;
    const int q     = lane >> 2;
    const int r2q   = (lane & 3) * 2;
    const int r4q   = (lane & 3) * 4;

    const float4* nf4 = (const float4*)nf;
    const int nTiles = (N + 127) >> 7;
    const int node = tid >> 1;
    const int hh   = tid & 1;

    for (int tile = blockIdx.x; tile < nTiles; tile += gridDim.x) {
        const int n0 = tile << 7;
        const int nn = min(128, N - n0);

        // ---- stage x = [agg/den | nf] as fp16 [128][K2P] ----
        {
            const int gn = min(n0 + node, N - 1);
            half* hr = xa + node * K2P;
            if (hh == 0) {
                float invd = 1.f / fmaxf(g_den[gn], 1e-38f);
                const float4* pa = &g_agg4[(size_t)gn * 16];
#pragma unroll
                for (int qq = 0; qq < 16; qq++) {
                    float4 v = pa[qq];
                    v.x *= invd; v.y *= invd; v.z *= invd; v.w *= invd;
                    conv_store4(hr + 4 * qq, v);
                }
            } else {
                const float4* pn = nf4 + (size_t)gn * 16;
#pragma unroll
                for (int qq = 0; qq < 16; qq++)
                    conv_store4(hr + 64 + 4 * qq, pn[qq]);
            }
        }
        __syncthreads();

        // ---- layer 1: D[128][128] ----
        float acc[4][4][4];
#pragma unroll
        for (int mt = 0; mt < 4; mt++)
#pragma unroll
            for (int nt = 0; nt < 4; nt++)
#pragma unroll
                for (int j = 0; j < 4; j++) acc[mt][nt][j] = 0.f;

        uint32_t ah_addr[4];
#pragma unroll
        for (int mt = 0; mt < 4; mt++) {
            int row = warp_m * 64 + mt * 16 + row_l;
            ah_addr[mt] = smem_base + NXA + (uint32_t)(row * K2P + kb) * 2;
        }

#pragma unroll 1
        for (int ks = 0; ks < 8; ks++) {
            const int k0 = ks * 16;
            uint32_t ah[4][4];
#pragma unroll
            for (int mt = 0; mt < 4; mt++)
                ldsm4(ah[mt][0], ah[mt][1], ah[mt][2], ah[mt][3],
                      ah_addr[mt] + k0 * 2);
#pragma unroll
            for (int nt = 0; nt < 4; nt++) {
                const half* bp =
                    wb1 + (warp_n * 32 + nt * 8 + q) * K2P + k0 + r4q;
                uint2 bu = *(const uint2*)(bp);
#pragma unroll
                for (int mt = 0; mt < 4; mt++)
                    mma16816(acc[mt][nt], ah[mt], bu.x, bu.y);
            }
        }
        __syncthreads();

        // ---- h = relu(D + bn1) -> fp16 in place ----
#pragma unroll
        for (int mt = 0; mt < 4; mt++) {
            int er = warp_m * 64 + mt * 16 + q;
#pragma unroll
            for (int nt = 0; nt < 4; nt++) {
                int c = warp_n * 32 + nt * 8 + r2q;
                float bb0 = b1s[c], bb1 = b1s[c + 1];
                float v0 = fmaxf(acc[mt][nt][0] + bb0, 0.f);
                float v1 = fmaxf(acc[mt][nt][1] + bb1, 0.f);
                float v2 = fmaxf(acc[mt][nt][2] + bb0, 0.f);
                float v3 = fmaxf(acc[mt][nt][3] + bb1, 0.f);
                *(half2*)(xa + er * K2P + c) = __floats2half2_rn(v0, v1);
                *(half2*)(xa + (er + 8) * K2P + c) = __floats2half2_rn(v2, v3);
            }
        }
        __syncthreads();

        // ---- layer 2: D2[128][64] ----
        float acc2[4][2][4];
#pragma unroll
        for (int mt = 0; mt < 4; mt++)
#pragma unroll
            for (int nt = 0; nt < 2; nt++)
#pragma unroll
                for (int j = 0; j < 4; j++) acc2[mt][nt][j] = 0.f;

#pragma unroll 1
        for (int ks = 0; ks < 8; ks++) {
            const int k0 = ks * 16;
            uint32_t ah[4][4];
#pragma unroll
            for (int mt = 0; mt < 4; mt++)
                ldsm4(ah[mt][0], ah[mt][1], ah[mt][2], ah[mt][3],
                      ah_addr[mt] + k0 * 2);
#pragma unroll
            for (int nt = 0; nt < 2; nt++) {
                const half* bp =
                    wb2 + (warp_n * 16 + nt * 8 + q) * K2P + k0 + r4q;
                uint2 bu = *(const uint2*)(bp);
#pragma unroll
                for (int mt = 0; mt < 4; mt++)
                    mma16816(acc2[mt][nt], ah[mt], bu.x, bu.y);
            }
        }

        // ---- store uh_n ----
#pragma unroll
        for (int mt = 0; mt < 4; mt++) {
            int er = warp_m * 64 + mt * 16 + q;
#pragma unroll
            for (int nt = 0; nt < 2; nt++) {
                int c = warp_n * 16 + nt * 8 + r2q;
                float bb0 = b2s[c], bb1 = b2s[c + 1];
                if (er < nn)
                    *(float2*)&outN[(size_t)(n0 + er) * 64 + c] =
                        make_float2(acc2[mt][nt][0] + bb0,
                                    acc2[mt][nt][1] + bb1);
                if (er + 8 < nn)
                    *(float2*)&outN[(size_t)(n0 + er + 8) * 64 + c] =
                        make_float2(acc2[mt][nt][2] + bb0,
                                    acc2[mt][nt][3] + bb1);
            }
        }
        __syncthreads();
    }
}

// ---------------------------------------------------------------------------
extern "C" void kernel_launch(void* const* d_in, const int* in_sizes, int n_in,
                              void* d_out, int out_size) {
    const float* nf  = (const float*)d_in[0];
    const float* ef  = (const float*)d_in[1];
    const int*   src = (const int*)d_in[2];
    const int*   dst = (const int*)d_in[3];
    const float* We1 = (const float*)d_in[4];
    const float* be1 = (const float*)d_in[5];
    const float* We2 = (const float*)d_in[6];
    const float* be2 = (const float*)d_in[7];
    const float* Wa1 = (const float*)d_in[8];
    const float* ba1 = (const float*)d_in[9];
    const float* Wa2 = (const float*)d_in[10];
    const float* ba2 = (const float*)d_in[11];
    const float* Wn1 = (const float*)d_in[12];
    const float* bn1 = (const float*)d_in[13];
    const float* Wn2 = (const float*)d_in[14];
    const float* bn2 = (const float*)d_in[15];

    int E = in_sizes[2];
    int N = in_sizes[0] / 64;
    if (E > E_MAX) E = E_MAX;
    if (N > N_MAX) N = N_MAX;

    float* outN = (float*)d_out;
    float* outE = outN + (size_t)N * 64;

    cudaFuncSetAttribute(edge_kernel,
                         cudaFuncAttributeMaxDynamicSharedMemorySize,
                         SMEM_EDGE_BYTES);
    cudaFuncSetAttribute(node_kernel,
                         cudaFuncAttributeMaxDynamicSharedMemorySize,
                         SMEM_NODE_BYTES);

    int nsm = 148;
    cudaDeviceGetAttribute(&nsm, cudaDevAttrMultiProcessorCount, 0);

    init_kernel<<<(N * 16 + 255) / 256, 256>>>(N);
    edge_kernel<<<nsm, 256, SMEM_EDGE_BYTES>>>(
        nf, ef, src, dst, We1, be1, We2, be2, Wa1, ba1, Wa2, ba2, outE, E);
    node_kernel<<<2 * nsm, 256, SMEM_NODE_BYTES>>>(
        nf, Wn1, bn1, Wn2, bn2, outN, N);
}